// round 1
// baseline (speedup 1.0000x reference)
#include <cuda_runtime.h>
#include <cstdint>

// ---------------------------------------------------------------------------
// Scratch buffers (static __device__ globals — no allocation allowed).
//   A: 33.55M floats (134MB)  B: 67.11M floats (268MB)  C: 33.55M floats
// ---------------------------------------------------------------------------
__device__ float g_bufA[33554432];
__device__ float g_bufB[67108864];
__device__ float g_bufC[33554432];

// ---------------------------------------------------------------------------
// Direct 3x3 conv, pad=1, stride templated. NCHW / OIHW, cross-correlation.
// Block: (8,16)=128 threads. Each block: 32(w) x 16(h) output tile for one
// batch image and a group of 8 output channels. Each thread: 4 consecutive
// output pixels (along w) x 8 couts = 32 accumulators.
// Smem: input tile for current cin + all weights for the cout group.
// ---------------------------------------------------------------------------
template<int STRIDE>
__global__ __launch_bounds__(128)
void conv3x3_kernel(const float* __restrict__ in, const float* __restrict__ w,
                    const float* __restrict__ bias, float* __restrict__ out,
                    int Cin, int Cout, int Hin, int Win, int do_relu)
{
    constexpr int TW = 32, TH = 16;
    constexpr int TIW = TW * STRIDE + 2;   // 34 (s1) / 66 (s2)
    constexpr int TIH = TH * STRIDE + 2;   // 18 (s1) / 34 (s2)
    constexpr int COG = 8;
    constexpr int WR  = 4 * STRIDE + 2;    // per-thread input row width

    __shared__ float s_tile[TIH * TIW];
    __shared__ float s_w[COG * 64 * 9];    // supports Cin up to 64

    const int Hout = Hin / STRIDE, Wout = Win / STRIDE;
    const int tx = threadIdx.x;            // 0..7
    const int ty = threadIdx.y;            // 0..15
    const int tid = ty * 8 + tx;
    const int groups = Cout / COG;
    const int g = blockIdx.z % groups;
    const int b = blockIdx.z / groups;

    // Preload all weights for this cout group (contiguous chunk in OIHW).
    {
        const float* wsrc = w + (size_t)g * COG * Cin * 9;
        const int wn = COG * Cin * 9;
        for (int i = tid; i < wn; i += 128) s_w[i] = wsrc[i];
    }

    float acc[COG][4];
    #pragma unroll
    for (int co = 0; co < COG; co++) {
        float bv = bias ? bias[g * COG + co] : 0.0f;
        #pragma unroll
        for (int px = 0; px < 4; px++) acc[co][px] = bv;
    }

    const int y0 = blockIdx.y * TH * STRIDE - 1;
    const int x0 = blockIdx.x * TW * STRIDE - 1;

    for (int ci = 0; ci < Cin; ci++) {
        __syncthreads();  // protects s_tile reuse (and first-iter weight preload)
        const float* ip = in + ((size_t)b * Cin + ci) * Hin * Win;
        for (int i = tid; i < TIH * TIW; i += 128) {
            int r = i / TIW, cidx = i % TIW;
            int gy = y0 + r, gx = x0 + cidx;
            float v = 0.0f;
            if (gy >= 0 && gy < Hin && gx >= 0 && gx < Win)
                v = ip[(size_t)gy * Win + gx];
            s_tile[i] = v;
        }
        __syncthreads();

        float rin[3][WR];
        #pragma unroll
        for (int dy = 0; dy < 3; dy++)
            #pragma unroll
            for (int j = 0; j < WR; j++)
                rin[dy][j] = s_tile[(ty * STRIDE + dy) * TIW + tx * 4 * STRIDE + j];

        const float* wc = s_w + ci * 9;
        #pragma unroll
        for (int co = 0; co < COG; co++) {
            const float* wp = wc + co * Cin * 9;
            #pragma unroll
            for (int dy = 0; dy < 3; dy++) {
                #pragma unroll
                for (int dx = 0; dx < 3; dx++) {
                    float wv = wp[dy * 3 + dx];
                    #pragma unroll
                    for (int px = 0; px < 4; px++)
                        acc[co][px] = fmaf(rin[dy][px * STRIDE + dx], wv, acc[co][px]);
                }
            }
        }
    }

    const int oy = blockIdx.y * TH + ty;
    const int ox = blockIdx.x * TW + tx * 4;
    #pragma unroll
    for (int co = 0; co < COG; co++) {
        float4 v = make_float4(acc[co][0], acc[co][1], acc[co][2], acc[co][3]);
        if (do_relu) {
            v.x = fmaxf(v.x, 0.0f); v.y = fmaxf(v.y, 0.0f);
            v.z = fmaxf(v.z, 0.0f); v.w = fmaxf(v.w, 0.0f);
        }
        *reinterpret_cast<float4*>(
            out + (((size_t)b * Cout + g * COG + co) * Hout + oy) * Wout + ox) = v;
    }
}

// ---------------------------------------------------------------------------
// ConvOffset2D bilinear sampling. Faithful to the torch-style raw reshape:
//   off[b*C+c, h, w, k] = off_linear[b*2C*HW + 2c*HW + 2*(h*W+w) + k]
// r = clip(off0+h, 0, H-1), c = clip(off1+w, 0, W-1), floor/ceil bilinear.
// ---------------------------------------------------------------------------
__global__ void deform_kernel(const float* __restrict__ x,
                              const float* __restrict__ off,
                              float* __restrict__ out,
                              int C, int H, int W, int total)
{
    int idx = blockIdx.x * blockDim.x + threadIdx.x;
    if (idx >= total) return;
    int w = idx % W;
    int h = (idx / W) % H;
    int c = (idx / (W * H)) % C;
    int b = idx / (W * H * C);

    size_t HW = (size_t)H * W;
    size_t obase = ((size_t)b * 2 * C + 2 * c) * HW + 2 * ((size_t)h * W + w);
    float o0 = off[obase];
    float o1 = off[obase + 1];

    float r  = fminf(fmaxf(o0 + (float)h, 0.0f), (float)(H - 1));
    float cc = fminf(fmaxf(o1 + (float)w, 0.0f), (float)(W - 1));
    float r0f = floorf(r), c0f = floorf(cc);
    int r0 = (int)r0f;
    int r1 = (int)ceilf(r);
    int c0 = (int)c0f;
    int c1 = (int)ceilf(cc);

    const float* xb = x + ((size_t)b * C + c) * HW;
    float v_lt = xb[(size_t)r0 * W + c0];
    float v_rb = xb[(size_t)r1 * W + c1];
    float v_lb = xb[(size_t)r0 * W + c1];
    float v_rt = xb[(size_t)r1 * W + c0];
    float fr = r - r0f;
    float fc = cc - c0f;
    float vt = v_lt + (v_rt - v_lt) * fr;
    float vb = v_lb + (v_rb - v_lb) * fr;
    out[idx] = vt + (vb - vt) * fc;
}

// ---------------------------------------------------------------------------
// Global average pool over H*W. One block per (b, c).
// ---------------------------------------------------------------------------
__global__ void avgpool_kernel(const float* __restrict__ in,
                               float* __restrict__ out, int HW)
{
    const float* p = in + (size_t)blockIdx.x * HW;
    float s = 0.0f;
    for (int i = threadIdx.x; i < HW; i += blockDim.x) s += p[i];
    __shared__ float sm[256];
    sm[threadIdx.x] = s;
    __syncthreads();
    for (int st = 128; st > 0; st >>= 1) {
        if (threadIdx.x < st) sm[threadIdx.x] += sm[threadIdx.x + st];
        __syncthreads();
    }
    if (threadIdx.x == 0) out[blockIdx.x] = sm[0] / (float)HW;
}

// ---------------------------------------------------------------------------
// Launch pipeline. All graph-capturable: kernel launches only.
// ---------------------------------------------------------------------------
extern "C" void kernel_launch(void* const* d_in, const int* in_sizes, int n_in,
                              void* d_out, int out_size)
{
    const float* x   = (const float*)d_in[0];
    const float* w1  = (const float*)d_in[1];
    const float* b1  = (const float*)d_in[2];
    const float* ow1 = (const float*)d_in[3];
    const float* w2  = (const float*)d_in[4];
    const float* b2  = (const float*)d_in[5];
    const float* ow2 = (const float*)d_in[6];
    const float* w3  = (const float*)d_in[7];
    const float* b3  = (const float*)d_in[8];
    const float* ow3 = (const float*)d_in[9];
    const float* w4  = (const float*)d_in[10];
    const float* b4  = (const float*)d_in[11];
    float* outp = (float*)d_out;

    float *A, *B, *C;
    cudaGetSymbolAddress((void**)&A, g_bufA);
    cudaGetSymbolAddress((void**)&B, g_bufB);
    cudaGetSymbolAddress((void**)&C, g_bufC);

    const dim3 blk(8, 16);

    // 1) conv1: x(16,32,256,256) -> A (16,32,256,256), relu
    conv3x3_kernel<1><<<dim3(8, 16, 16 * 4), blk>>>(x, w1, b1, A, 32, 32, 256, 256, 1);

    // 2) offconv1: A -> B (16,64,256,256), no bias, no relu
    conv3x3_kernel<1><<<dim3(8, 16, 16 * 8), blk>>>(A, ow1, nullptr, B, 32, 64, 256, 256, 0);

    // 3) deform1: sample A with offsets B -> C (16,32,256,256)
    {
        int total = 16 * 32 * 256 * 256;
        deform_kernel<<<total / 256, 256>>>(A, B, C, 32, 256, 256, total);
    }

    // 4) conv2 stride2: C -> A (16,64,128,128), relu
    conv3x3_kernel<2><<<dim3(4, 8, 16 * 8), blk>>>(C, w2, b2, A, 32, 64, 256, 256, 1);

    // 5) offconv2: A -> B (16,128,128,128)
    conv3x3_kernel<1><<<dim3(4, 8, 16 * 16), blk>>>(A, ow2, nullptr, B, 64, 128, 128, 128, 0);

    // 6) deform2: A,B -> C (16,64,128,128)
    {
        int total = 16 * 64 * 128 * 128;
        deform_kernel<<<total / 256, 256>>>(A, B, C, 64, 128, 128, total);
    }

    // 7) conv3 stride2: C -> A (16,32,64,64), relu
    conv3x3_kernel<2><<<dim3(2, 4, 16 * 4), blk>>>(C, w3, b3, A, 64, 32, 128, 128, 1);

    // 8) offconv3: A -> B (16,64,64,64)
    conv3x3_kernel<1><<<dim3(2, 4, 16 * 8), blk>>>(A, ow3, nullptr, B, 32, 64, 64, 64, 0);

    // 9) deform3: A,B -> C (16,32,64,64)
    {
        int total = 16 * 32 * 64 * 64;
        deform_kernel<<<total / 256, 256>>>(A, B, C, 32, 64, 64, total);
    }

    // 10) conv4 stride2: C -> A (16,32,32,32), relu
    conv3x3_kernel<2><<<dim3(1, 2, 16 * 4), blk>>>(C, w4, b4, A, 32, 32, 64, 64, 1);

    // 11) global avg pool: A -> out (16,32,1,1) = 512 floats
    avgpool_kernel<<<512, 256>>>(A, outp, 32 * 32);
}